// round 3
// baseline (speedup 1.0000x reference)
#include <cuda_runtime.h>
#include <cstdint>

#define BB 64
#define TT 1024
#define DD 64
#define HH 256
#define NGROUPS 8
#define NSLICES 16
#define BPG 8      // batches per group (cluster)
#define UPS 16     // hidden units per slice (CTA)
#define NCTAS (NGROUPS*NSLICES)
#define NT 512

// ---------------- device-global scratch (no runtime allocation allowed) ----------------
__device__ float d_h1s[(size_t)TT * BB * HH];   // layer-0 hidden stream [T][B][H]
__device__ float d_h2s[BB * HH];                // layer-1 final hidden [B][H]

__device__ __forceinline__ uint32_t s2u(const void* p) {
    uint32_t a;
    asm("{ .reg .u64 t; cvta.to.shared.u64 t, %1; cvt.u32.u64 %0, t; }" : "=r"(a) : "l"(p));
    return a;
}
__device__ __forceinline__ void cluster_sync_() {
    asm volatile("barrier.cluster.arrive.aligned;" ::: "memory");
    asm volatile("barrier.cluster.wait.aligned;" ::: "memory");
}
__device__ __forceinline__ uint32_t ctarank_() {
    uint32_t r; asm("mov.u32 %0, %%cluster_ctarank;" : "=r"(r)); return r;
}
__device__ __forceinline__ unsigned long long splat2(float w) {
    unsigned long long d; asm("mov.b64 %0, {%1, %1};" : "=l"(d) : "f"(w)); return d;
}
__device__ __forceinline__ void fma2(unsigned long long& d, unsigned long long a, unsigned long long b) {
    asm("fma.rn.f32x2 %0, %1, %2, %0;" : "+l"(d) : "l"(a), "l"(b));
}
__device__ __forceinline__ float sigf(float x)   { return 1.f / (1.f + __expf(-x)); }
__device__ __forceinline__ float tanhfs(float x) { return 1.f - 2.f / (1.f + __expf(2.f * x)); }

// One LSTM layer, persistent, one 16-CTA cluster per batch group of 8.
// CTA owns 64 gate rows (4 gates x 16 units) for 8 batches.
// Input vector sV is k-major [KTOT][8 batches] (32B rows), double-buffered;
// each CTA pushes its h slice into all peers' next-buffer via DSMEM stores.
template <int KIN>
__global__ void __launch_bounds__(NT, 1) rnn_layer(
    const float* __restrict__ xin, long long SB, long long ST,
    const float* __restrict__ Wih, const float* __restrict__ Whh,
    const float* __restrict__ bih, const float* __restrict__ bhh,
    int in_sel, int out_sel)
{
    constexpr int KTOT = KIN + HH;
    constexpr int SP   = KTOT + 4;     // weight row stride (floats); %32==4 -> 4-wf LDS.128
    constexpr int KQ   = KTOT / 8;     // per-thread k span (8-way k split)
    constexpr int PST  = 64 * 12;      // partial-sum per-kq stride (row pad 12 -> 16B aligned)

    extern __shared__ float sm[];
    float* sW  = sm;                   // [64][SP]
    float* sV0 = sW + 64 * SP;         // [KTOT][8]
    float* sV1 = sV0 + KTOT * 8;       // [KTOT][8]
    float* sP  = sV1 + KTOT * 8;       // [8][64*12]
    float* sC  = sP + 8 * PST;         // [128]  cell state (u*8+b)
    float* sB  = sC + 128;             // [64]   combined bias
    float* sH  = sB + 64;              // [16][8] h staging for scatter

    const float* in = in_sel ? d_h1s : xin;
    float*       hs = out_sel ? d_h2s : d_h1s;
    const int stream_all = !out_sel;

    const uint32_t rank = ctarank_();
    const int grp   = blockIdx.x >> 4;
    const int bbase = grp * BPG;
    const int ubase = (int)rank * UPS;
    const int tid   = threadIdx.x;

    // ---- one-time: combined weight slice [64][KIN | H] into SMEM ----
    for (int idx = tid; idx < 64 * KTOT; idx += NT) {
        int r = idx / KTOT, k = idx - r * KTOT;
        int R = ((r >> 4) << 8) + ubase + (r & 15);
        sW[r * SP + k] = (k < KIN) ? Wih[(long long)R * KIN + k]
                                   : Whh[(long long)R * HH + (k - KIN)];
    }
    if (tid < 64) {
        int R = ((tid >> 4) << 8) + ubase + (tid & 15);
        sB[tid] = bih[R] + bhh[R];
    }
    if (tid < 128) sC[tid] = 0.f;
    for (int idx = tid; idx < HH * 8; idx += NT) sV0[KIN * 8 + idx] = 0.f;  // h_{-1}=0

    // x staging mapping: thread -> (batch pb, k-quad pk4); layer0 uses first 128 threads
    const int pb  = tid & 7;
    const int pk4 = tid >> 3;
    const float* pin = in + (long long)(bbase + pb) * SB;

    if ((KIN == DD) ? (tid < 128) : true) {      // stage x_0
        float4 v = *reinterpret_cast<const float4*>(pin + pk4 * 4);
        float* d = sV0 + pk4 * 32 + pb;
        d[0] = v.x; d[8] = v.y; d[16] = v.z; d[24] = v.w;
    }
    __syncthreads();
    cluster_sync_();

    const int rr = tid & 63;           // gate row
    const int kq = tid >> 6;           // k octant (uniform per warp)
    const float* wrow = sW + rr * SP + kq * KQ;
    const uint32_t sV0u = s2u(sV0), sV1u = s2u(sV1);
    const int s_peer = tid >> 5;               // scatter: peer CTA 0..15 (uniform per warp)
    const int s_u    = (tid & 31) >> 1;        // unit 0..15
    const int s_half = tid & 1;                // float4 half of the 8-batch row

    for (int t = 0; t < TT; ++t) {
        float* svp = (t & 1) ? sV1 : sV0;
        float* svn = (t & 1) ? sV0 : sV1;
        const uint32_t svn_u = (t & 1) ? sV0u : sV1u;

        // prefetch x_{t+1} into registers (hidden behind compute)
        float4 xr;
        const bool dopf = (t + 1 < TT) && ((KIN == DD) ? (tid < 128) : true);
        if (dopf) xr = *reinterpret_cast<const float4*>(pin + (long long)(t + 1) * ST + pk4 * 4);

        // ---- gates: thread = 1 row x 8 batches (4 x f32x2 accums) over its k octant ----
        const float* vb = svp + kq * KQ * 8;
        unsigned long long a0 = 0, a1 = 0, a2 = 0, a3 = 0;
#pragma unroll 2
        for (int k = 0; k < KQ; k += 4) {
            float4 w4 = *reinterpret_cast<const float4*>(wrow + k);
            {
                const ulonglong2* v = reinterpret_cast<const ulonglong2*>(vb + (k + 0) * 8);
                ulonglong2 qa = v[0], qb = v[1];
                unsigned long long ws = splat2(w4.x);
                fma2(a0, ws, qa.x); fma2(a1, ws, qa.y); fma2(a2, ws, qb.x); fma2(a3, ws, qb.y);
            }
            {
                const ulonglong2* v = reinterpret_cast<const ulonglong2*>(vb + (k + 1) * 8);
                ulonglong2 qa = v[0], qb = v[1];
                unsigned long long ws = splat2(w4.y);
                fma2(a0, ws, qa.x); fma2(a1, ws, qa.y); fma2(a2, ws, qb.x); fma2(a3, ws, qb.y);
            }
            {
                const ulonglong2* v = reinterpret_cast<const ulonglong2*>(vb + (k + 2) * 8);
                ulonglong2 qa = v[0], qb = v[1];
                unsigned long long ws = splat2(w4.z);
                fma2(a0, ws, qa.x); fma2(a1, ws, qa.y); fma2(a2, ws, qb.x); fma2(a3, ws, qb.y);
            }
            {
                const ulonglong2* v = reinterpret_cast<const ulonglong2*>(vb + (k + 3) * 8);
                ulonglong2 qa = v[0], qb = v[1];
                unsigned long long ws = splat2(w4.w);
                fma2(a0, ws, qa.x); fma2(a1, ws, qa.y); fma2(a2, ws, qb.x); fma2(a3, ws, qb.y);
            }
        }
        {
            ulonglong2* pp = reinterpret_cast<ulonglong2*>(sP + kq * PST + rr * 12);
            pp[0] = make_ulonglong2(a0, a1);
            pp[1] = make_ulonglong2(a2, a3);
        }
        if (dopf) {  // commit x_{t+1} into next buffer (x-part; peers write only h-part)
            float* d = svn + pk4 * 32 + pb;
            d[0] = xr.x; d[8] = xr.y; d[16] = xr.z; d[24] = xr.w;
        }
        __syncthreads();

        // ---- fused reduce + elementwise: thread = (unit u, batch b) ----
        if (tid < 128) {
            int u = tid >> 3, b = tid & 7;
            float gv[4];
#pragma unroll
            for (int g = 0; g < 4; ++g) {
                int r = g * 16 + u;
                float s = sB[r];
#pragma unroll
                for (int q = 0; q < 8; ++q) s += sP[q * PST + r * 12 + b];
                gv[g] = s;
            }
            float iv = sigf(gv[0]);
            float fv = sigf(gv[1]);
            float gg = tanhfs(gv[2]);
            float ov = sigf(gv[3]);
            float c  = fv * sC[tid] + iv * gg;
            sC[tid] = c;
            float hv = ov * tanhfs(c);
            sH[u * 8 + b] = hv;
            if (stream_all)      hs[(size_t)t * (BB * HH) + (size_t)(bbase + b) * HH + ubase + u] = hv;
            else if (t == TT - 1) hs[(size_t)(bbase + b) * HH + ubase + u] = hv;
        }
        __syncthreads();

        // ---- DSMEM scatter: push my h slice (16u x 8b) into all 16 peers' next buffer ----
        {
            uint32_t rbase;
            asm volatile("mapa.shared::cluster.u32 %0, %1, %2;"
                         : "=r"(rbase) : "r"(svn_u), "r"(s_peer));
            const float* src = sH + s_u * 8 + s_half * 4;
            uint32_t dst = rbase + (uint32_t)(((KIN + ubase + s_u) * 8 + s_half * 4) * 4);
            asm volatile("st.shared::cluster.f32 [%0], %1;"     :: "r"(dst),      "f"(src[0]) : "memory");
            asm volatile("st.shared::cluster.f32 [%0+4], %1;"   :: "r"(dst),      "f"(src[1]) : "memory");
            asm volatile("st.shared::cluster.f32 [%0+8], %1;"   :: "r"(dst),      "f"(src[2]) : "memory");
            asm volatile("st.shared::cluster.f32 [%0+12], %1;"  :: "r"(dst),      "f"(src[3]) : "memory");
        }
        cluster_sync_();   // release my stores, acquire peers' -> sV(next) complete
    }
}

// out[b] = dot(h2_last[b][:], fc_w) + fc_b
__global__ void fc_kernel(const float* __restrict__ fcw,
                          const float* __restrict__ fcb,
                          float* __restrict__ out)
{
    int b = blockIdx.x, tid = threadIdx.x;
    const float* h = d_h2s + (size_t)b * HH;
    float s = 0.f;
    for (int k = tid; k < HH; k += 128) s += h[k] * fcw[k];
    for (int o = 16; o > 0; o >>= 1) s += __shfl_xor_sync(0xFFFFFFFFu, s, o);
    __shared__ float ws[4];
    if ((tid & 31) == 0) ws[tid >> 5] = s;
    __syncthreads();
    if (tid == 0) out[b] = ws[0] + ws[1] + ws[2] + ws[3] + fcb[0];
}

extern "C" void kernel_launch(void* const* d_in, const int* in_sizes, int n_in,
                              void* d_out, int out_size)
{
    const float* x     = (const float*)d_in[0];
    const float* W_ih0 = (const float*)d_in[1];
    const float* W_hh0 = (const float*)d_in[2];
    const float* b_ih0 = (const float*)d_in[3];
    const float* b_hh0 = (const float*)d_in[4];
    const float* W_ih1 = (const float*)d_in[5];
    const float* W_hh1 = (const float*)d_in[6];
    const float* b_ih1 = (const float*)d_in[7];
    const float* b_hh1 = (const float*)d_in[8];
    const float* fc_w  = (const float*)d_in[9];
    const float* fc_b  = (const float*)d_in[10];
    float* out = (float*)d_out;

    // dynamic SMEM (bytes): sW + 2*sV + sP + sC + sB + sH
    const int sm0 = (64 * (DD + HH + 4) + 2 * (DD + HH) * 8 + 8 * 64 * 12 + 128 + 64 + 128) * 4; // 129,280
    const int sm1 = (64 * (HH + HH + 4) + 2 * (HH + HH) * 8 + 8 * 64 * 12 + 128 + 64 + 128) * 4; // 190,720

    cudaFuncSetAttribute(rnn_layer<DD>, cudaFuncAttributeMaxDynamicSharedMemorySize, sm0);
    cudaFuncSetAttribute(rnn_layer<DD>, cudaFuncAttributeNonPortableClusterSizeAllowed, 1);
    cudaFuncSetAttribute(rnn_layer<HH>, cudaFuncAttributeMaxDynamicSharedMemorySize, sm1);
    cudaFuncSetAttribute(rnn_layer<HH>, cudaFuncAttributeNonPortableClusterSizeAllowed, 1);

    cudaLaunchAttribute attrs[1];
    attrs[0].id = cudaLaunchAttributeClusterDimension;
    attrs[0].val.clusterDim = {NSLICES, 1, 1};

    cudaLaunchConfig_t cfg = {};
    cfg.gridDim = dim3(NCTAS, 1, 1);
    cfg.blockDim = dim3(NT, 1, 1);
    cfg.stream = 0;
    cfg.attrs = attrs;
    cfg.numAttrs = 1;

    // Layer 0: input = x [B][T][D] -> SB = T*D, ST = D
    cfg.dynamicSmemBytes = sm0;
    cudaLaunchKernelEx(&cfg, rnn_layer<DD>,
                       x, (long long)TT * DD, (long long)DD,
                       W_ih0, W_hh0, b_ih0, b_hh0, 0, 0);

    // Layer 1: input = d_h1s [T][B][H] -> SB = H, ST = B*H
    cfg.dynamicSmemBytes = sm1;
    cudaLaunchKernelEx(&cfg, rnn_layer<HH>,
                       (const float*)nullptr, (long long)HH, (long long)BB * HH,
                       W_ih1, W_hh1, b_ih1, b_hh1, 1, 1);

    fc_kernel<<<BB, 128>>>(fc_w, fc_b, out);
}

// round 4
// speedup vs baseline: 2.4706x; 2.4706x over previous
#include <cuda_runtime.h>
#include <cstdint>

#define BB 64
#define TT 1024
#define DD 64
#define HH 256
#define NGRP 4        // batch groups per layer (16 batches each)
#define NSL 16        // slices per group (16 units each)
#define NBAT 16       // batches per group
#define NT 256        // threads per CTA

typedef unsigned long long ull;

// ---------------- device-global scratch ----------------
__device__ float    d_h1s[(size_t)TT * BB * HH];   // layer-0 hidden stream [T][B][H]
__device__ float    d_hb0[2 * BB * HH];            // layer-0 h ping-pong
__device__ float    d_hb1[2 * BB * HH];            // layer-1 h ping-pong
__device__ float    d_h2s[BB * HH];                // layer-1 final h [B][H]
__device__ unsigned d_cnt[8 * 32];                 // per (layer,group) barrier counters
__device__ unsigned d_gen[8 * 32];                 // per (layer,group) generations (monotonic)
__device__ unsigned d_prog[NGRP];                  // layer-0 -> layer-1 progress (reset by l1 at exit)

// Span-16 generation barrier. Last arriver optionally publishes progress.
__device__ __forceinline__ void gbar(int gid, volatile unsigned* prog, unsigned val) {
    __syncthreads();
    if (threadIdx.x == 0) {
        __threadfence();
        unsigned* cnt = &d_cnt[gid * 32];
        unsigned* gen = &d_gen[gid * 32];
        unsigned my = *(volatile unsigned*)gen;
        if (atomicAdd(cnt, 1u) == NSL - 1) {
            atomicExch(cnt, 0u);
            __threadfence();
            if (prog) *prog = val;
            atomicAdd(gen, 1u);
        } else {
            while (*(volatile unsigned*)gen == my) __nanosleep(32);
        }
        __threadfence();
    }
    __syncthreads();
}

__device__ __forceinline__ ull splat2(float w) {
    ull d; asm("mov.b64 %0, {%1, %1};" : "=l"(d) : "f"(w)); return d;
}
__device__ __forceinline__ void fma2(ull& d, ull a, ull b) {
    asm("fma.rn.f32x2 %0, %1, %2, %0;" : "+l"(d) : "l"(a), "l"(b));
}
__device__ __forceinline__ float sigf(float x)   { return 1.f / (1.f + __expf(-x)); }
__device__ __forceinline__ float tanhfs(float x) { return 1.f - 2.f / (1.f + __expf(2.f * x)); }

// One LSTM layer, persistent. CTA = 16 units x 16 batches (64 gate rows).
// gates = [x_t | h_{t-1}] @ [W_ih | W_hh]^T + bias.  8-way k split across warps,
// thread = 2 rows x 16 batches (f32x2 pairs) x KQ.
template <int KIN>
__device__ __forceinline__ void layer_body(
    const float* __restrict__ in0, long long inSB, long long inST,
    const float* __restrict__ Wih, const float* __restrict__ Whh,
    const float* __restrict__ bih, const float* __restrict__ bhh,
    float* hbuf, float* hstream, float* hlast,
    int grp, int slice, int gid,
    volatile unsigned* prog_w, volatile unsigned* prog_r)
{
    constexpr int KTOT = KIN + HH;
    constexpr int SP   = KTOT + 4;      // weight row stride
    constexpr int KQ   = KTOT / 8;      // per-warp k span
    constexpr int KT1  = KTOT + 4;      // sT row stride (16B aligned)
    constexpr int PK   = 64 * 18;       // sP per-warp stride

    extern __shared__ float sm[];
    float* sW = sm;                     // [64][SP]
    float* sV = sW + 64 * SP;           // [KTOT][16]  k-major input
    float* sP = sV + KTOT * 16;         // [8][64][18] partials; staging scratch sT aliased here
    float* sB = sP + 8 * PK;            // [64] bias
    float* sC = sB + 64;                // [256] cell state (b*16+u)
    float* sT = sP;                     // [16][KT1] staging scratch (dead when sP live)

    const int tid   = threadIdx.x;
    const int bbase = grp * NBAT;
    const int ubase = slice * 16;

    // ---- one-time: weights, bias ----
    for (int idx = tid; idx < 64 * KTOT; idx += NT) {
        int r = idx / KTOT, k = idx - r * KTOT;
        int R = ((r >> 4) << 8) + ubase + (r & 15);
        sW[r * SP + k] = (k < KIN) ? Wih[(long long)R * KIN + k]
                                   : Whh[(long long)R * HH + (k - KIN)];
    }
    if (tid < 64) {
        int R = ((tid >> 4) << 8) + ubase + (tid & 15);
        sB[tid] = bih[R] + bhh[R];
    }
    sC[tid] = 0.f;
    {   // zero own slice of hbuf[0]
        int b = tid >> 4, u = tid & 15;
        hbuf[(bbase + b) * HH + ubase + u] = 0.f;
    }
    __threadfence();
    gbar(gid, nullptr, 0);

    const int w    = tid >> 5;          // warp = k octant
    const int lane = tid & 31;
    const float* wA = sW + lane * SP + w * KQ;
    const float* wB = sW + (lane + 32) * SP + w * KQ;
    const float* vb = sV + w * KQ * 16;

    for (int t = 0; t < TT; ++t) {
        const float* hrd = hbuf + (t & 1) * (BB * HH);
        float*       hwr = hbuf + ((t ^ 1) & 1) * (BB * HH);

        // ---- layer-1: wait for layer-0 to publish h1[t] ----
        if (prog_r) {
            if (tid == 0) {
                while (*prog_r < (unsigned)(t + 1)) __nanosleep(32);
                __threadfence();
            }
            __syncthreads();
        }

        // ---- staging phase A: coalesced copy into sT[b][k] ----
        {
            constexpr int K4 = KIN / 4;
            for (int idx = tid; idx < NBAT * K4; idx += NT) {
                int b = idx / K4, k4 = idx - b * K4;
                float4 v = *reinterpret_cast<const float4*>(
                    in0 + (long long)(bbase + b) * inSB + (long long)t * inST + 4 * k4);
                *reinterpret_cast<float4*>(sT + b * KT1 + 4 * k4) = v;
            }
            constexpr int H4 = HH / 4;
            for (int idx = tid; idx < NBAT * H4; idx += NT) {
                int b = idx / H4, k4 = idx - b * H4;
                float4 v = *reinterpret_cast<const float4*>(hrd + (bbase + b) * HH + 4 * k4);
                *reinterpret_cast<float4*>(sT + b * KT1 + KIN + 4 * k4) = v;
            }
        }
        __syncthreads();

        // ---- staging phase B: transpose sT[b][k] -> sV[k][16b] ----
        for (int idx = tid; idx < KTOT * 16; idx += NT) {
            int k = idx >> 4, b = idx & 15;
            sV[k * 16 + b] = sT[b * KT1 + k];
        }
        __syncthreads();   // sT dead; sP may now be written

        // ---- gates: thread = 2 rows x 16 batches over its k octant ----
        {
            ull aA[8], aB[8];
#pragma unroll
            for (int i = 0; i < 8; ++i) { aA[i] = 0; aB[i] = 0; }
#pragma unroll 2
            for (int c = 0; c < KQ / 4; ++c) {
                float4 wa = *reinterpret_cast<const float4*>(wA + 4 * c);
                float4 wb = *reinterpret_cast<const float4*>(wB + 4 * c);
                const float* vk = vb + 4 * c * 16;
#pragma unroll
                for (int j = 0; j < 4; ++j) {
                    const ulonglong2* vp = reinterpret_cast<const ulonglong2*>(vk + j * 16);
                    ulonglong2 q0 = vp[0], q1 = vp[1], q2 = vp[2], q3 = vp[3];
                    float fa = (j == 0) ? wa.x : (j == 1) ? wa.y : (j == 2) ? wa.z : wa.w;
                    float fb = (j == 0) ? wb.x : (j == 1) ? wb.y : (j == 2) ? wb.z : wb.w;
                    ull wsa = splat2(fa), wsb = splat2(fb);
                    fma2(aA[0], wsa, q0.x); fma2(aA[1], wsa, q0.y);
                    fma2(aA[2], wsa, q1.x); fma2(aA[3], wsa, q1.y);
                    fma2(aA[4], wsa, q2.x); fma2(aA[5], wsa, q2.y);
                    fma2(aA[6], wsa, q3.x); fma2(aA[7], wsa, q3.y);
                    fma2(aB[0], wsb, q0.x); fma2(aB[1], wsb, q0.y);
                    fma2(aB[2], wsb, q1.x); fma2(aB[3], wsb, q1.y);
                    fma2(aB[4], wsb, q2.x); fma2(aB[5], wsb, q2.y);
                    fma2(aB[6], wsb, q3.x); fma2(aB[7], wsb, q3.y);
                }
            }
            ull* pA = reinterpret_cast<ull*>(sP + w * PK + lane * 18);
            ull* pB = reinterpret_cast<ull*>(sP + w * PK + (lane + 32) * 18);
#pragma unroll
            for (int bp = 0; bp < 8; ++bp) { pA[bp] = aA[bp]; pB[bp] = aB[bp]; }
        }
        __syncthreads();

        // ---- fused reduce + pointwise: thread = (batch b, unit u) ----
        {
            int b = tid >> 4, u = tid & 15;
            float gv[4];
#pragma unroll
            for (int g = 0; g < 4; ++g) {
                int r = g * 16 + u;
                float s = sB[r];
#pragma unroll
                for (int q = 0; q < 8; ++q) s += sP[q * PK + r * 18 + b];
                gv[g] = s;
            }
            float iv = sigf(gv[0]);
            float fv = sigf(gv[1]);
            float gg = tanhfs(gv[2]);
            float ov = sigf(gv[3]);
            float c  = fv * sC[tid] + iv * gg;
            sC[tid] = c;
            float hv = ov * tanhfs(c);
            hwr[(bbase + b) * HH + ubase + u] = hv;
            if (hstream) hstream[((size_t)t * BB + bbase + b) * HH + ubase + u] = hv;
            if (hlast && t == TT - 1) hlast[(size_t)(bbase + b) * HH + ubase + u] = hv;
        }
        __threadfence();
        gbar(gid, prog_w, (unsigned)(t + 1));
    }

    // layer-1: reset progress flag for the next launch (all slices are past final read)
    if (prog_r && slice == 0 && tid == 0) *prog_r = 0;
}

__global__ void __launch_bounds__(NT, 1) rnn_fused(
    const float* __restrict__ x,
    const float* __restrict__ Wih0, const float* __restrict__ Whh0,
    const float* __restrict__ bih0, const float* __restrict__ bhh0,
    const float* __restrict__ Wih1, const float* __restrict__ Whh1,
    const float* __restrict__ bih1, const float* __restrict__ bhh1)
{
    int bid   = blockIdx.x;
    int layer = bid >> 6;
    int sub   = bid & 63;
    int grp   = sub >> 4;
    int slice = sub & 15;
    int gid   = bid >> 4;     // 0..7 = (layer, grp)

    if (layer == 0) {
        layer_body<DD>(x, (long long)TT * DD, (long long)DD,
                       Wih0, Whh0, bih0, bhh0,
                       d_hb0, d_h1s, nullptr,
                       grp, slice, gid, &d_prog[grp], nullptr);
    } else {
        layer_body<HH>(d_h1s, (long long)HH, (long long)BB * HH,
                       Wih1, Whh1, bih1, bhh1,
                       d_hb1, nullptr, d_h2s,
                       grp, slice, gid, nullptr, &d_prog[grp]);
    }
}

// out[b] = dot(h2_last[b][:], fc_w) + fc_b
__global__ void fc_kernel(const float* __restrict__ fcw,
                          const float* __restrict__ fcb,
                          float* __restrict__ out)
{
    int b = blockIdx.x, tid = threadIdx.x;
    const float* h = d_h2s + (size_t)b * HH;
    float s = 0.f;
    for (int k = tid; k < HH; k += 128) s += h[k] * fcw[k];
    for (int o = 16; o > 0; o >>= 1) s += __shfl_xor_sync(0xFFFFFFFFu, s, o);
    __shared__ float ws[4];
    if ((tid & 31) == 0) ws[tid >> 5] = s;
    __syncthreads();
    if (tid == 0) out[b] = ws[0] + ws[1] + ws[2] + ws[3] + fcb[0];
}

extern "C" void kernel_launch(void* const* d_in, const int* in_sizes, int n_in,
                              void* d_out, int out_size)
{
    const float* x     = (const float*)d_in[0];
    const float* W_ih0 = (const float*)d_in[1];
    const float* W_hh0 = (const float*)d_in[2];
    const float* b_ih0 = (const float*)d_in[3];
    const float* b_hh0 = (const float*)d_in[4];
    const float* W_ih1 = (const float*)d_in[5];
    const float* W_hh1 = (const float*)d_in[6];
    const float* b_ih1 = (const float*)d_in[7];
    const float* b_hh1 = (const float*)d_in[8];
    const float* fc_w  = (const float*)d_in[9];
    const float* fc_b  = (const float*)d_in[10];
    float* out = (float*)d_out;

    // smem for layer-1 layout (the larger): (64*516 + 512*16 + 8*64*18 + 64 + 256) * 4
    const int SMB = (64 * (HH + HH + 4) + (HH + HH) * 16 + 8 * 64 * 18 + 64 + 256) * 4; // 203,008

    cudaFuncSetAttribute(rnn_fused, cudaFuncAttributeMaxDynamicSharedMemorySize, SMB);

    rnn_fused<<<128, NT, SMB>>>(x, W_ih0, W_hh0, b_ih0, b_hh0,
                                   W_ih1, W_hh1, b_ih1, b_hh1);
    fc_kernel<<<BB, 128>>>(fc_w, fc_b, out);
}

// round 5
// speedup vs baseline: 2.7963x; 1.1318x over previous
#include <cuda_runtime.h>
#include <cstdint>

#define BB 64
#define TT 1024
#define DD 64
#define HH 256
#define NGRP 4        // batch groups per layer (16 batches each)
#define NSL 16        // slices per group
#define NBAT 16       // batches per group
#define NT 256

typedef unsigned long long ull;

// ---------------- device-global scratch ----------------
__device__ float    d_xT[(size_t)TT * NGRP * DD * 16];    // x transposed [T][grp][D][16b]
__device__ float    d_h1s[(size_t)TT * NGRP * HH * 16];   // l0 hidden stream k-major [T][grp][H][16b]
__device__ float    d_hbA[4 * NGRP * HH * 16];            // l0 h rotation [4][grp][H][16b]
__device__ float    d_hbB[4 * NGRP * HH * 16];            // l1 h rotation
__device__ float    d_h2s[BB * HH];                       // l1 final h [B][H]
__device__ unsigned d_flag[2 * NGRP * 16];                // monotonic per-slice progress

__device__ __forceinline__ ull splat2(float w) {
    ull d; asm("mov.b64 %0, {%1, %1};" : "=l"(d) : "f"(w)); return d;
}
__device__ __forceinline__ void fma2(ull& d, ull a, ull b) {
    asm("fma.rn.f32x2 %0, %1, %2, %0;" : "+l"(d) : "l"(a), "l"(b));
}
__device__ __forceinline__ float sigf(float x)   { return 1.f / (1.f + __expf(-x)); }
__device__ __forceinline__ float tanhfs(float x) { return 1.f - 2.f / (1.f + __expf(2.f * x)); }

// one-time x transpose: x[B][T][D] -> d_xT[T][grp][D][16b]
__global__ void __launch_bounds__(256, 4) xpose(const float* __restrict__ x) {
    __shared__ float sX[64 * 68];
    const int t = blockIdx.x, tid = threadIdx.x;
#pragma unroll
    for (int i = 0; i < 4; ++i) {
        int b = tid >> 2, k4 = (tid & 3) + 4 * i;     // k4: float4 index 0..15
        float4 v = *reinterpret_cast<const float4*>(x + ((size_t)b * TT + t) * DD + k4 * 4);
        *reinterpret_cast<float4*>(sX + b * 68 + k4 * 4) = v;
    }
    __syncthreads();
    const int g = tid >> 6, k = tid & 63;
#pragma unroll
    for (int q = 0; q < 4; ++q) {
        float4 o;
        o.x = sX[(g * 16 + q * 4 + 0) * 68 + k];
        o.y = sX[(g * 16 + q * 4 + 1) * 68 + k];
        o.z = sX[(g * 16 + q * 4 + 2) * 68 + k];
        o.w = sX[(g * 16 + q * 4 + 3) * 68 + k];
        *reinterpret_cast<float4*>(d_xT + (((size_t)t * NGRP + g) * DD + k) * 16 + q * 4) = o;
    }
}

// One LSTM layer, persistent. CTA = 16 units x 16 batches (64 gate rows),
// 8-way k split across warps, thread = 2 rows x 16 batches (f32x2).
template <int KIN, int LAYER>
__device__ __forceinline__ void layer_body(
    const float* __restrict__ in0,           // k-major stream [T][grp][KIN][16]
    const float* __restrict__ Wih, const float* __restrict__ Whh,
    const float* __restrict__ bih, const float* __restrict__ bhh,
    float* hb, float* hstream, int grp, int slice)
{
    constexpr int KTOT = KIN + HH;
    constexpr int SP   = KTOT + 4;      // weight row stride; SP%32==4 -> conflict-free LDS.128
    constexpr int KQ   = KTOT / 8;
    constexpr int PK   = 64 * 18;

    extern __shared__ float sm[];
    float* sW = sm;                     // [64][SP]
    float* sV = sW + 64 * SP;           // [KTOT][16]
    float* sP = sV + KTOT * 16;         // [8][64][18]
    float* sB = sP + 8 * PK;            // [64]
    float* sC = sB + 64;                // [256] cell (b*16+u)
    float* sH = sC + 256;               // [16][17] h staging

    const int tid   = threadIdx.x;
    const int bbase = grp * NBAT;
    const int ubase = slice * 16;
    unsigned* myflag = &d_flag[(LAYER * NGRP + grp) * 16 + slice];

    // base: all flags advance by exactly TT+1 per launch (both layers) -> lockstep
    const unsigned fbase = *(volatile unsigned*)myflag;

    for (int idx = tid; idx < 64 * KTOT; idx += NT) {
        int r = idx / KTOT, k = idx - r * KTOT;
        int R = ((r >> 4) << 8) + ubase + (r & 15);
        sW[r * SP + k] = (k < KIN) ? Wih[(long long)R * KIN + k]
                                   : Whh[(long long)R * HH + (k - KIN)];
    }
    if (tid < 64) {
        int R = ((tid >> 4) << 8) + ubase + (tid & 15);
        sB[tid] = bih[R] + bhh[R];
    }
    sC[tid] = 0.f;
    if (tid < 64) {   // zero own slice of rotation buffer 0 (h_{-1})
        float4 z = make_float4(0.f, 0.f, 0.f, 0.f);
        int u = tid >> 2, q = tid & 3;
        *reinterpret_cast<float4*>(hb + ((size_t)(0 * NGRP + grp) * HH + ubase + u) * 16 + q * 4) = z;
    }
    __syncthreads();
    if (tid == 0) {
        __threadfence();
        *(volatile unsigned*)myflag = fbase + 1;      // init done
    }

    const int w    = tid >> 5;
    const int lane = tid & 31;
    const float* wA = sW + lane * SP + w * KQ;
    const float* wB = sW + (lane + 32) * SP + w * KQ;
    const float* vb = sV + w * KQ * 16;

    for (int t = 0; t < TT; ++t) {
        // ---- wait: own peers past step t-1; (l1) l0 past step t ----
        if (tid < 16) {
            volatile unsigned* f = &d_flag[(LAYER * NGRP + grp) * 16 + tid];
            unsigned tgt = fbase + (unsigned)t + 1u;
            while (*f < tgt) {}
        } else if (LAYER == 1 && tid < 32) {
            volatile unsigned* f = &d_flag[grp * 16 + (tid - 16)];
            unsigned tgt = fbase + (unsigned)t + 2u;
            while (*f < tgt) {}
        }
        __syncthreads();

        // ---- stage sV (straight copy; inputs already k-major) ----
        {
            const float4* sx = reinterpret_cast<const float4*>(in0 + (size_t)(t * NGRP + grp) * KIN * 16);
            const float4* sh = reinterpret_cast<const float4*>(hb + (size_t)(((t & 3) * NGRP) + grp) * HH * 16);
            float4* dv = reinterpret_cast<float4*>(sV);
            if (LAYER == 0) {
                for (int i = tid; i < KIN * 4; i += NT) dv[i] = sx[i];               // x: stable, L1 ok
            } else {
                for (int i = tid; i < KIN * 4; i += NT) dv[i] = __ldcv(sx + i);      // cross-SM
            }
            for (int i = tid; i < HH * 4; i += NT) dv[KIN * 4 + i] = __ldcv(sh + i); // cross-SM
        }
        __syncthreads();

        // ---- gates: thread = 2 rows x 16 batches over its k octant ----
        {
            ull aA[8], aB[8];
#pragma unroll
            for (int i = 0; i < 8; ++i) { aA[i] = 0; aB[i] = 0; }
#pragma unroll 2
            for (int c = 0; c < KQ / 4; ++c) {
                float4 wa = *reinterpret_cast<const float4*>(wA + 4 * c);
                float4 wb = *reinterpret_cast<const float4*>(wB + 4 * c);
                const float* vk = vb + 4 * c * 16;
#pragma unroll
                for (int j = 0; j < 4; ++j) {
                    const ulonglong2* vp = reinterpret_cast<const ulonglong2*>(vk + j * 16);
                    ulonglong2 q0 = vp[0], q1 = vp[1], q2 = vp[2], q3 = vp[3];
                    float fa = (j == 0) ? wa.x : (j == 1) ? wa.y : (j == 2) ? wa.z : wa.w;
                    float fb = (j == 0) ? wb.x : (j == 1) ? wb.y : (j == 2) ? wb.z : wb.w;
                    ull wsa = splat2(fa), wsb = splat2(fb);
                    fma2(aA[0], wsa, q0.x); fma2(aA[1], wsa, q0.y);
                    fma2(aA[2], wsa, q1.x); fma2(aA[3], wsa, q1.y);
                    fma2(aA[4], wsa, q2.x); fma2(aA[5], wsa, q2.y);
                    fma2(aA[6], wsa, q3.x); fma2(aA[7], wsa, q3.y);
                    fma2(aB[0], wsb, q0.x); fma2(aB[1], wsb, q0.y);
                    fma2(aB[2], wsb, q1.x); fma2(aB[3], wsb, q1.y);
                    fma2(aB[4], wsb, q2.x); fma2(aB[5], wsb, q2.y);
                    fma2(aB[6], wsb, q3.x); fma2(aB[7], wsb, q3.y);
                }
            }
            ull* pA = reinterpret_cast<ull*>(sP + w * PK + lane * 18);
            ull* pB = reinterpret_cast<ull*>(sP + w * PK + (lane + 32) * 18);
#pragma unroll
            for (int bp = 0; bp < 8; ++bp) { pA[bp] = aA[bp]; pB[bp] = aB[bp]; }
        }
        __syncthreads();

        // ---- fused reduce + pointwise: thread = (batch b, unit u) ----
        {
            int b = tid >> 4, u = tid & 15;
            float gv[4];
#pragma unroll
            for (int g = 0; g < 4; ++g) {
                int r = g * 16 + u;
                float s = sB[r];
#pragma unroll
                for (int q = 0; q < 8; ++q) s += sP[q * PK + r * 18 + b];
                gv[g] = s;
            }
            float iv = sigf(gv[0]);
            float fv = sigf(gv[1]);
            float gg = tanhfs(gv[2]);
            float ov = sigf(gv[3]);
            float c  = fv * sC[tid] + iv * gg;
            sC[tid] = c;
            float hv = ov * tanhfs(c);
            sH[u * 17 + b] = hv;
            if (LAYER == 1 && t == TT - 1)
                d_h2s[(size_t)(bbase + b) * HH + ubase + u] = hv;
        }
        __syncthreads();

        // ---- publish h slice k-major (coalesced 64B rows) ----
        if (tid < 64) {
            int u = tid >> 2, q = tid & 3;
            float4 v;
            v.x = sH[u * 17 + q * 4 + 0];
            v.y = sH[u * 17 + q * 4 + 1];
            v.z = sH[u * 17 + q * 4 + 2];
            v.w = sH[u * 17 + q * 4 + 3];
            *reinterpret_cast<float4*>(
                hb + ((size_t)((((t + 1) & 3) * NGRP) + grp) * HH + ubase + u) * 16 + q * 4) = v;
            if (LAYER == 0)
                *reinterpret_cast<float4*>(
                    hstream + ((size_t)(t * NGRP + grp) * HH + ubase + u) * 16 + q * 4) = v;
        }
        __syncthreads();
        if (tid == 0) {
            __threadfence();
            *(volatile unsigned*)myflag = fbase + (unsigned)t + 2u;   // step t done
        }
    }
}

__global__ void __launch_bounds__(NT, 1) rnn_fused(
    const float* __restrict__ Wih0, const float* __restrict__ Whh0,
    const float* __restrict__ bih0, const float* __restrict__ bhh0,
    const float* __restrict__ Wih1, const float* __restrict__ Whh1,
    const float* __restrict__ bih1, const float* __restrict__ bhh1)
{
    int bid   = blockIdx.x;
    int layer = bid >> 6;
    int sub   = bid & 63;
    int grp   = sub >> 4;
    int slice = sub & 15;

    if (layer == 0) {
        layer_body<DD, 0>(d_xT, Wih0, Whh0, bih0, bhh0, d_hbA, d_h1s, grp, slice);
    } else {
        layer_body<HH, 1>(d_h1s, Wih1, Whh1, bih1, bhh1, d_hbB, nullptr, grp, slice);
    }
}

// out[b] = dot(h2_last[b][:], fc_w) + fc_b
__global__ void fc_kernel(const float* __restrict__ fcw,
                          const float* __restrict__ fcb,
                          float* __restrict__ out)
{
    int b = blockIdx.x, tid = threadIdx.x;
    const float* h = d_h2s + (size_t)b * HH;
    float s = 0.f;
    for (int k = tid; k < HH; k += 128) s += h[k] * fcw[k];
    for (int o = 16; o > 0; o >>= 1) s += __shfl_xor_sync(0xFFFFFFFFu, s, o);
    __shared__ float ws[4];
    if ((tid & 31) == 0) ws[tid >> 5] = s;
    __syncthreads();
    if (tid == 0) out[b] = ws[0] + ws[1] + ws[2] + ws[3] + fcb[0];
}

extern "C" void kernel_launch(void* const* d_in, const int* in_sizes, int n_in,
                              void* d_out, int out_size)
{
    const float* x     = (const float*)d_in[0];
    const float* W_ih0 = (const float*)d_in[1];
    const float* W_hh0 = (const float*)d_in[2];
    const float* b_ih0 = (const float*)d_in[3];
    const float* b_hh0 = (const float*)d_in[4];
    const float* W_ih1 = (const float*)d_in[5];
    const float* W_hh1 = (const float*)d_in[6];
    const float* b_ih1 = (const float*)d_in[7];
    const float* b_hh1 = (const float*)d_in[8];
    const float* fc_w  = (const float*)d_in[9];
    const float* fc_b  = (const float*)d_in[10];
    float* out = (float*)d_out;

    // smem sized for layer-1 layout (the larger of the two template paths)
    const int SMB = (64 * (HH + HH + 4) + (HH + HH) * 16 + 8 * 64 * 18 + 64 + 256 + 16 * 17) * 4; // 204,096

    cudaFuncSetAttribute(rnn_fused, cudaFuncAttributeMaxDynamicSharedMemorySize, SMB);

    xpose<<<TT, 256>>>(x);
    rnn_fused<<<128, NT, SMB>>>(W_ih0, W_hh0, b_ih0, b_hh0,
                                W_ih1, W_hh1, b_ih1, b_hh1);
    fc_kernel<<<BB, 128>>>(fc_w, fc_b, out);
}

// round 6
// speedup vs baseline: 3.7419x; 1.3381x over previous
#include <cuda_runtime.h>
#include <cstdint>

#define BB 64
#define TT 1024
#define DD 64
#define HH 256
#define NGRP 4        // batch groups per layer (16 batches each)
#define NSL 16        // slices per group
#define NBAT 16       // batches per group
#define NT 256

typedef unsigned long long ull;

// ---------------- device-global scratch ----------------
__device__ float    d_xT[(size_t)TT * NGRP * DD * 16];    // x transposed [T][grp][D][16b]
__device__ float    d_h1s[(size_t)TT * NGRP * HH * 16];   // l0 hidden stream k-major [T][grp][H][16b]
__device__ float    d_hbA[4 * NGRP * HH * 16];            // l0 h rotation [4][grp][H][16b]
__device__ float    d_hbB[4 * NGRP * HH * 16];            // l1 h rotation
__device__ float    d_h2s[BB * HH];                       // l1 final h [B][H]
__device__ unsigned d_flag[2 * NGRP * 16];                // monotonic per-slice progress

__device__ __forceinline__ ull splat2(float w) {
    ull d; asm("mov.b64 %0, {%1, %1};" : "=l"(d) : "f"(w)); return d;
}
__device__ __forceinline__ void fma2(ull& d, ull a, ull b) {
    asm("fma.rn.f32x2 %0, %1, %2, %0;" : "+l"(d) : "l"(a), "l"(b));
}
__device__ __forceinline__ float sigf(float x)   { return 1.f / (1.f + __expf(-x)); }
__device__ __forceinline__ float tanhfs(float x) { return 1.f - 2.f / (1.f + __expf(2.f * x)); }

// one-time x transpose: x[B][T][D] -> d_xT[T][grp][D][16b]
__global__ void __launch_bounds__(256, 4) xpose(const float* __restrict__ x) {
    __shared__ float sX[64 * 68];
    const int t = blockIdx.x, tid = threadIdx.x;
#pragma unroll
    for (int i = 0; i < 4; ++i) {
        int b = tid >> 2, k4 = (tid & 3) + 4 * i;
        float4 v = *reinterpret_cast<const float4*>(x + ((size_t)b * TT + t) * DD + k4 * 4);
        *reinterpret_cast<float4*>(sX + b * 68 + k4 * 4) = v;
    }
    __syncthreads();
    const int g = tid >> 6, k = tid & 63;
#pragma unroll
    for (int q = 0; q < 4; ++q) {
        float4 o;
        o.x = sX[(g * 16 + q * 4 + 0) * 68 + k];
        o.y = sX[(g * 16 + q * 4 + 1) * 68 + k];
        o.z = sX[(g * 16 + q * 4 + 2) * 68 + k];
        o.w = sX[(g * 16 + q * 4 + 3) * 68 + k];
        *reinterpret_cast<float4*>(d_xT + (((size_t)t * NGRP + g) * DD + k) * 16 + q * 4) = o;
    }
}

// accumulate NCH chunks of 4 k-rows: 2 gate rows x 16 batches (f32x2 pairs)
template <int NCH>
__device__ __forceinline__ void gemm_part(const float* __restrict__ wA,
                                          const float* __restrict__ wB,
                                          const float* __restrict__ vk0,
                                          ull* aA, ull* aB)
{
#pragma unroll
    for (int c = 0; c < NCH; ++c) {
        float4 wa = *reinterpret_cast<const float4*>(wA + 4 * c);
        float4 wb = *reinterpret_cast<const float4*>(wB + 4 * c);
        const float* vk = vk0 + 4 * c * 16;
#pragma unroll
        for (int j = 0; j < 4; ++j) {
            const ulonglong2* vp = reinterpret_cast<const ulonglong2*>(vk + j * 16);
            ulonglong2 q0 = vp[0], q1 = vp[1], q2 = vp[2], q3 = vp[3];
            float fa = (j == 0) ? wa.x : (j == 1) ? wa.y : (j == 2) ? wa.z : wa.w;
            float fb = (j == 0) ? wb.x : (j == 1) ? wb.y : (j == 2) ? wb.z : wb.w;
            ull wsa = splat2(fa), wsb = splat2(fb);
            fma2(aA[0], wsa, q0.x); fma2(aA[1], wsa, q0.y);
            fma2(aA[2], wsa, q1.x); fma2(aA[3], wsa, q1.y);
            fma2(aA[4], wsa, q2.x); fma2(aA[5], wsa, q2.y);
            fma2(aA[6], wsa, q3.x); fma2(aA[7], wsa, q3.y);
            fma2(aB[0], wsb, q0.x); fma2(aB[1], wsb, q0.y);
            fma2(aB[2], wsb, q1.x); fma2(aB[3], wsb, q1.y);
            fma2(aB[4], wsb, q2.x); fma2(aB[5], wsb, q2.y);
            fma2(aB[6], wsb, q3.x); fma2(aB[7], wsb, q3.y);
        }
    }
}

// One LSTM layer, persistent. CTA = 16 units x 16 batches (64 gate rows).
// x-part of step t+1 is computed in the exchange window after publishing h[t].
template <int KIN, int LAYER>
__device__ __forceinline__ void layer_body(
    const float* __restrict__ in0,           // k-major input stream [T][grp][KIN][16]
    const float* __restrict__ Wih, const float* __restrict__ Whh,
    const float* __restrict__ bih, const float* __restrict__ bhh,
    float* hb, float* hstream, int grp, int slice)
{
    constexpr int KTOT = KIN + HH;
    constexpr int SP   = KTOT + 4;      // weight row stride
    constexpr int XQ   = KIN / 8;       // per-warp x-k span
    constexpr int HQ   = HH / 8;        // per-warp h-k span (32)
    constexpr int PK   = 64 * 18;

    extern __shared__ float sm[];
    float* sW = sm;                     // [64][SP]
    float* sV = sW + 64 * SP;           // [KTOT][16]  (x | h), k-major
    float* sP = sV + KTOT * 16;         // [8][64][18]
    float* sB = sP + 8 * PK;            // [64]
    float* sC = sB + 64;                // [256] cell (b*16+u)

    const int tid   = threadIdx.x;
    const int bbase = grp * NBAT;
    const int ubase = slice * 16;
    unsigned* myflag = &d_flag[(LAYER * NGRP + grp) * 16 + slice];
    const unsigned fbase = *(volatile unsigned*)myflag;   // lockstep across all flags

    for (int idx = tid; idx < 64 * KTOT; idx += NT) {
        int r = idx / KTOT, k = idx - r * KTOT;
        int R = ((r >> 4) << 8) + ubase + (r & 15);
        sW[r * SP + k] = (k < KIN) ? Wih[(long long)R * KIN + k]
                                   : Whh[(long long)R * HH + (k - KIN)];
    }
    if (tid < 64) {
        int R = ((tid >> 4) << 8) + ubase + (tid & 15);
        sB[tid] = bih[R] + bhh[R];
    }
    sC[tid] = 0.f;
    if (tid < 64) {   // zero own slice of rotation buffer 0 (h_{-1})
        float4 z = make_float4(0.f, 0.f, 0.f, 0.f);
        int u = tid >> 2, q = tid & 3;
        *reinterpret_cast<float4*>(hb + ((size_t)(0 * NGRP + grp) * HH + ubase + u) * 16 + q * 4) = z;
    }
    __syncthreads();
    if (tid == 0) {
        __threadfence();
        *(volatile unsigned*)myflag = fbase + 1;
    }

    const int w    = tid >> 5;
    const int lane = tid & 31;
    const float* wAx = sW + lane * SP + w * XQ;
    const float* wBx = sW + (lane + 32) * SP + w * XQ;
    const float* wAh = sW + lane * SP + KIN + w * HQ;
    const float* wBh = sW + (lane + 32) * SP + KIN + w * HQ;
    const float* vx  = sV + (w * XQ) * 16;
    const float* vh  = sV + (KIN + w * HQ) * 16;

    ull aA[8], aB[8];

    // ---- prologue: stage + compute x-part for t = 0 ----
    if (LAYER == 1 && tid < 16) {   // need stream[0]: l0 flag >= fbase+2
        volatile unsigned* f = &d_flag[grp * 16 + tid];
        while (*f < fbase + 2u) {}
    }
    __syncthreads();
    {
        const float4* sx = reinterpret_cast<const float4*>(in0 + (size_t)(0 * NGRP + grp) * KIN * 16);
        float4* dv = reinterpret_cast<float4*>(sV);
        if (LAYER == 0) for (int i = tid; i < KIN * 4; i += NT) dv[i] = sx[i];
        else            for (int i = tid; i < KIN * 4; i += NT) dv[i] = __ldcv(sx + i);
    }
    __syncthreads();
#pragma unroll
    for (int i = 0; i < 8; ++i) { aA[i] = 0; aB[i] = 0; }
    gemm_part<XQ / 4>(wAx, wBx, vx, aA, aB);

    for (int t = 0; t < TT; ++t) {
        // ---- wait for peers' h[t] ----
        if (tid < 16) {
            volatile unsigned* f = &d_flag[(LAYER * NGRP + grp) * 16 + tid];
            unsigned tgt = fbase + (unsigned)t + 1u;
            while (*f < tgt) {}
        }
        __syncthreads();

        // ---- stage h[t] ----
        {
            const float4* sh = reinterpret_cast<const float4*>(
                hb + (size_t)(((t & 3) * NGRP) + grp) * HH * 16);
            float4* dv = reinterpret_cast<float4*>(sV + KIN * 16);
            for (int i = tid; i < HH * 4; i += NT) dv[i] = __ldcv(sh + i);
        }
        __syncthreads();

        // ---- h-part compute (accumulate onto x-part), write partials ----
        gemm_part<HQ / 4>(wAh, wBh, vh, aA, aB);
        {
            ull* pA = reinterpret_cast<ull*>(sP + w * PK + lane * 18);
            ull* pB = reinterpret_cast<ull*>(sP + w * PK + (lane + 32) * 18);
#pragma unroll
            for (int bp = 0; bp < 8; ++bp) { pA[bp] = aA[bp]; pB[bp] = aB[bp]; }
        }
        __syncthreads();

        // ---- fused reduce + pointwise + direct publish ----
        {
            int b = tid >> 4, u = tid & 15;
            float gv[4];
#pragma unroll
            for (int g = 0; g < 4; ++g) {
                int r = g * 16 + u;
                float s = sB[r];
#pragma unroll
                for (int q = 0; q < 8; ++q) s += sP[q * PK + r * 18 + b];
                gv[g] = s;
            }
            float iv = sigf(gv[0]);
            float fv = sigf(gv[1]);
            float gg = tanhfs(gv[2]);
            float ov = sigf(gv[3]);
            float c  = fv * sC[tid] + iv * gg;
            sC[tid] = c;
            float hv = ov * tanhfs(c);
            hb[((size_t)((((t + 1) & 3) * NGRP) + grp) * HH + ubase + u) * 16 + b] = hv;
            if (LAYER == 0)
                hstream[((size_t)(t * NGRP + grp) * HH + ubase + u) * 16 + b] = hv;
            if (LAYER == 1 && t == TT - 1)
                d_h2s[(size_t)(bbase + b) * HH + ubase + u] = hv;
        }
        __syncthreads();    // all publish STGs issued; sP free

        // ---- release flag; poll next x availability (l1) in parallel ----
        if (tid == 0) {
            __threadfence();
            *(volatile unsigned*)myflag = fbase + (unsigned)t + 2u;
        }
        if (LAYER == 1 && t + 1 < TT && tid >= 32 && tid < 48) {
            volatile unsigned* f = &d_flag[grp * 16 + (tid - 32)];
            unsigned tgt = fbase + (unsigned)t + 3u;   // stream[t+1] ready
            while (*f < tgt) {}
        }
        __syncthreads();

        // ---- stage + compute x-part for t+1 (hides exchange window) ----
        if (t + 1 < TT) {
            const float4* sx = reinterpret_cast<const float4*>(
                in0 + (size_t)((t + 1) * NGRP + grp) * KIN * 16);
            float4* dv = reinterpret_cast<float4*>(sV);
            if (LAYER == 0) for (int i = tid; i < KIN * 4; i += NT) dv[i] = sx[i];
            else            for (int i = tid; i < KIN * 4; i += NT) dv[i] = __ldcv(sx + i);
            __syncthreads();
#pragma unroll
            for (int i = 0; i < 8; ++i) { aA[i] = 0; aB[i] = 0; }
            gemm_part<XQ / 4>(wAx, wBx, vx, aA, aB);
        }
    }
}

__global__ void __launch_bounds__(NT, 1) rnn_fused(
    const float* __restrict__ Wih0, const float* __restrict__ Whh0,
    const float* __restrict__ bih0, const float* __restrict__ bhh0,
    const float* __restrict__ Wih1, const float* __restrict__ Whh1,
    const float* __restrict__ bih1, const float* __restrict__ bhh1)
{
    int bid   = blockIdx.x;
    int layer = bid >> 6;
    int sub   = bid & 63;
    int grp   = sub >> 4;
    int slice = sub & 15;

    if (layer == 0) {
        layer_body<DD, 0>(d_xT, Wih0, Whh0, bih0, bhh0, d_hbA, d_h1s, grp, slice);
    } else {
        layer_body<HH, 1>(d_h1s, Wih1, Whh1, bih1, bhh1, d_hbB, nullptr, grp, slice);
    }
}

// out[b] = dot(h2_last[b][:], fc_w) + fc_b
__global__ void fc_kernel(const float* __restrict__ fcw,
                          const float* __restrict__ fcb,
                          float* __restrict__ out)
{
    int b = blockIdx.x, tid = threadIdx.x;
    const float* h = d_h2s + (size_t)b * HH;
    float s = 0.f;
    for (int k = tid; k < HH; k += 128) s += h[k] * fcw[k];
    for (int o = 16; o > 0; o >>= 1) s += __shfl_xor_sync(0xFFFFFFFFu, s, o);
    __shared__ float ws[4];
    if ((tid & 31) == 0) ws[tid >> 5] = s;
    __syncthreads();
    if (tid == 0) out[b] = ws[0] + ws[1] + ws[2] + ws[3] + fcb[0];
}

extern "C" void kernel_launch(void* const* d_in, const int* in_sizes, int n_in,
                              void* d_out, int out_size)
{
    const float* x     = (const float*)d_in[0];
    const float* W_ih0 = (const float*)d_in[1];
    const float* W_hh0 = (const float*)d_in[2];
    const float* b_ih0 = (const float*)d_in[3];
    const float* b_hh0 = (const float*)d_in[4];
    const float* W_ih1 = (const float*)d_in[5];
    const float* W_hh1 = (const float*)d_in[6];
    const float* b_ih1 = (const float*)d_in[7];
    const float* b_hh1 = (const float*)d_in[8];
    const float* fc_w  = (const float*)d_in[9];
    const float* fc_b  = (const float*)d_in[10];
    float* out = (float*)d_out;

    // smem sized for layer-1 layout: sW + sV + sP + sB + sC
    const int SMB = (64 * (HH + HH + 4) + (HH + HH) * 16 + 8 * 64 * 18 + 64 + 256) * 4; // 203,008

    cudaFuncSetAttribute(rnn_fused, cudaFuncAttributeMaxDynamicSharedMemorySize, SMB);

    xpose<<<TT, 256>>>(x);
    rnn_fused<<<128, NT, SMB>>>(W_ih0, W_hh0, b_ih0, b_hh0,
                                W_ih1, W_hh1, b_ih1, b_hh1);
    fc_kernel<<<BB, 128>>>(fc_w, fc_b, out);
}

// round 7
// speedup vs baseline: 4.7137x; 1.2597x over previous
#include <cuda_runtime.h>
#include <cstdint>

#define BB 64
#define TT 1024
#define DD 64
#define HH 256
#define NGRP 4        // batch groups per layer (16 batches each)
#define NBAT 16       // batches per group
#define NT 256

typedef unsigned long long ull;

// ---------------- device-global scratch ----------------
__device__ float    d_h1s[(size_t)TT * NGRP * HH * 16];   // l0 hidden stream k-major [T][grp][H][16b]
__device__ float    d_hbA[4 * NGRP * HH * 16];            // l0 h rotation [4][grp][H][16b]
__device__ float    d_hbB[4 * NGRP * HH * 16];            // l1 h rotation
__device__ float    d_h2s[BB * HH];                       // l1 final h [B][H]
__device__ unsigned d_flag[2 * NGRP * 16];                // monotonic per-slice progress

__device__ __forceinline__ ull splat2(float w) {
    ull d; asm("mov.b64 %0, {%1, %1};" : "=l"(d) : "f"(w)); return d;
}
__device__ __forceinline__ void fma2(ull& d, ull a, ull b) {
    asm("fma.rn.f32x2 %0, %1, %2, %0;" : "+l"(d) : "l"(a), "l"(b));
}
__device__ __forceinline__ float sigf(float x)   { return 1.f / (1.f + __expf(-x)); }
__device__ __forceinline__ float tanhfs(float x) { return 1.f - 2.f / (1.f + __expf(2.f * x)); }
__device__ __forceinline__ void st_release(unsigned* p, unsigned v) {
    asm volatile("st.global.release.gpu.u32 [%0], %1;" :: "l"(p), "r"(v) : "memory");
}
__device__ __forceinline__ unsigned ld_acquire(const unsigned* p) {
    unsigned v; asm volatile("ld.global.acquire.gpu.u32 %0, [%1];" : "=r"(v) : "l"(p)); return v;
}

// wait (lanes 0,1) until flags[s0] and flags[s0+1] reach tgt, then warp-converge
__device__ __forceinline__ void wait2(const unsigned* flags, int s0, unsigned tgt, int lane) {
    if (lane < 2) {
        const unsigned* f = flags + s0 + lane;
        while (ld_acquire(f) < tgt) {}
    }
    __syncwarp(0xFFFFFFFFu);
}

// accumulate NCH chunks of 4 k-rows: 2 gate rows x 16 batches (f32x2 pairs)
template <int NCH>
__device__ __forceinline__ void gemm_part(const float* __restrict__ wA,
                                          const float* __restrict__ wB,
                                          const float* __restrict__ vk0,
                                          ull* aA, ull* aB)
{
#pragma unroll
    for (int c = 0; c < NCH; ++c) {
        float4 wa = *reinterpret_cast<const float4*>(wA + 4 * c);
        float4 wb = *reinterpret_cast<const float4*>(wB + 4 * c);
        const float* vk = vk0 + 4 * c * 16;
#pragma unroll
        for (int j = 0; j < 4; ++j) {
            const ulonglong2* vp = reinterpret_cast<const ulonglong2*>(vk + j * 16);
            ulonglong2 q0 = vp[0], q1 = vp[1], q2 = vp[2], q3 = vp[3];
            float fa = (j == 0) ? wa.x : (j == 1) ? wa.y : (j == 2) ? wa.z : wa.w;
            float fb = (j == 0) ? wb.x : (j == 1) ? wb.y : (j == 2) ? wb.z : wb.w;
            ull wsa = splat2(fa), wsb = splat2(fb);
            fma2(aA[0], wsa, q0.x); fma2(aA[1], wsa, q0.y);
            fma2(aA[2], wsa, q1.x); fma2(aA[3], wsa, q1.y);
            fma2(aA[4], wsa, q2.x); fma2(aA[5], wsa, q2.y);
            fma2(aA[6], wsa, q3.x); fma2(aA[7], wsa, q3.y);
            fma2(aB[0], wsb, q0.x); fma2(aB[1], wsb, q0.y);
            fma2(aB[2], wsb, q1.x); fma2(aB[3], wsb, q1.y);
            fma2(aB[4], wsb, q2.x); fma2(aB[5], wsb, q2.y);
            fma2(aB[6], wsb, q3.x); fma2(aB[7], wsb, q3.y);
        }
    }
}

// One LSTM layer, persistent. CTA = 16 units x 16 batches (64 gate rows).
// Per-warp dependency tracking: warp w consumes h slices {2w, 2w+1} only.
template <int KIN, int LAYER>
__device__ __forceinline__ void layer_body(
    const float* __restrict__ in0,           // l0: x [B][T][D]; l1: d_h1s k-major [T][grp][H][16]
    const float* __restrict__ Wih, const float* __restrict__ Whh,
    const float* __restrict__ bih, const float* __restrict__ bhh,
    float* hb, float* hstream, int grp, int slice)
{
    constexpr int KTOT = KIN + HH;
    constexpr int SP   = KTOT + 4;      // weight row stride
    constexpr int XQ   = KIN / 8;       // per-warp x-k span (l0: 8, l1: 32)
    constexpr int HQ   = HH / 8;        // per-warp h-k span (32)
    constexpr int PK   = 64 * 18;

    extern __shared__ float sm[];
    float* sW = sm;                     // [64][SP]
    float* sV = sW + 64 * SP;           // [KTOT][16]  (x | h), k-major
    float* sP = sV + KTOT * 16;         // [8][64][18]
    float* sB = sP + 8 * PK;            // [64]
    float* sC = sB + 64;                // [256] cell (b*16+u)

    const int tid   = threadIdx.x;
    const int bbase = grp * NBAT;
    const int ubase = slice * 16;
    unsigned* ownflags = &d_flag[(LAYER * NGRP + grp) * 16];
    unsigned* srcflags = &d_flag[grp * 16];               // layer-0 flags (l1 x-dep)
    unsigned* myflag   = ownflags + slice;
    const unsigned fbase = *(volatile unsigned*)myflag;   // lockstep across all flags

    for (int idx = tid; idx < 64 * KTOT; idx += NT) {
        int r = idx / KTOT, k = idx - r * KTOT;
        int R = ((r >> 4) << 8) + ubase + (r & 15);
        sW[r * SP + k] = (k < KIN) ? Wih[(long long)R * KIN + k]
                                   : Whh[(long long)R * HH + (k - KIN)];
    }
    if (tid < 64) {
        int R = ((tid >> 4) << 8) + ubase + (tid & 15);
        sB[tid] = bih[R] + bhh[R];
    }
    sC[tid] = 0.f;
    if (tid < 64) {   // zero own slice of rotation buffer 0 (h_{-1})
        float4 z = make_float4(0.f, 0.f, 0.f, 0.f);
        int u = tid >> 2, q = tid & 3;
        *reinterpret_cast<float4*>(hb + ((size_t)(0 * NGRP + grp) * HH + ubase + u) * 16 + q * 4) = z;
    }
    __syncthreads();
    if (tid == 0) st_release(myflag, fbase + 1);

    const int w    = tid >> 5;
    const int lane = tid & 31;
    const float* wAx = sW + lane * SP + w * XQ;
    const float* wBx = sW + (lane + 32) * SP + w * XQ;
    const float* wAh = sW + lane * SP + KIN + w * HQ;
    const float* wBh = sW + (lane + 32) * SP + KIN + w * HQ;
    const float* vx  = sV + (w * XQ) * 16;
    const float* vh  = sV + (KIN + w * HQ) * 16;

    // per-warp x staging (l0: direct transpose from x; l1: k-major copy)
    const float* xsrc0 = in0 + (size_t)(bbase + (lane >> 1)) * TT * DD + w * XQ + (lane & 1) * 4;
    float* xdst0 = sV + (w * XQ + (lane & 1) * 4) * 16 + (lane >> 1);

    ull aA[8], aB[8];

    // ---- prologue: x-part for t = 0 ----
#pragma unroll
    for (int i = 0; i < 8; ++i) { aA[i] = 0; aB[i] = 0; }
    if (LAYER == 1) wait2(srcflags, 2 * w, fbase + 2u, lane);
    if (LAYER == 0) {
        float4 v = *reinterpret_cast<const float4*>(xsrc0);
        xdst0[0] = v.x; xdst0[16] = v.y; xdst0[32] = v.z; xdst0[48] = v.w;
    } else {
        const float4* src = reinterpret_cast<const float4*>(in0) + ((size_t)(0 * NGRP + grp) * KIN + w * XQ) * 4;
        float4* dst = reinterpret_cast<float4*>(sV) + (w * XQ) * 4;
#pragma unroll
        for (int i = 0; i < XQ / 8; ++i) dst[lane + 32 * i] = __ldcv(src + lane + 32 * i);
    }
    __syncwarp(0xFFFFFFFFu);
    gemm_part<XQ / 4>(wAx, wBx, vx, aA, aB);

    for (int t = 0; t < TT; ++t) {
        // ---- [A] per-warp: wait own-layer source slices, stage h chunk, h-gemm ----
        wait2(ownflags, 2 * w, fbase + (unsigned)t + 1u, lane);
        {
            const float4* src = reinterpret_cast<const float4*>(hb) +
                                ((size_t)((t & 3) * NGRP + grp) * HH + w * HQ) * 4;
            float4* dst = reinterpret_cast<float4*>(sV) + (KIN + w * HQ) * 4;
#pragma unroll
            for (int i = 0; i < HQ / 8; ++i) dst[lane + 32 * i] = __ldcv(src + lane + 32 * i);
        }
        __syncwarp(0xFFFFFFFFu);
        gemm_part<HQ / 4>(wAh, wBh, vh, aA, aB);
        {
            ull* pA = reinterpret_cast<ull*>(sP + w * PK + lane * 18);
            ull* pB = reinterpret_cast<ull*>(sP + w * PK + (lane + 32) * 18);
#pragma unroll
            for (int bp = 0; bp < 8; ++bp) { pA[bp] = aA[bp]; pB[bp] = aB[bp]; }
        }
        __syncthreads();

        // ---- [C] fused reduce + pointwise + publish ----
        {
            int b = tid >> 4, u = tid & 15;
            float gv[4];
#pragma unroll
            for (int g = 0; g < 4; ++g) {
                int r = g * 16 + u;
                float s = sB[r];
#pragma unroll
                for (int q = 0; q < 8; ++q) s += sP[q * PK + r * 18 + b];
                gv[g] = s;
            }
            float iv = sigf(gv[0]);
            float fv = sigf(gv[1]);
            float gg = tanhfs(gv[2]);
            float ov = sigf(gv[3]);
            float c  = fv * sC[tid] + iv * gg;
            sC[tid] = c;
            float hv = ov * tanhfs(c);
            hb[((size_t)((((t + 1) & 3) * NGRP) + grp) * HH + ubase + u) * 16 + b] = hv;
            if (LAYER == 0)
                hstream[((size_t)(t * NGRP + grp) * HH + ubase + u) * 16 + b] = hv;
            if (LAYER == 1 && t == TT - 1)
                d_h2s[(size_t)(bbase + b) * HH + ubase + u] = hv;
        }
        __syncthreads();            // publish issued by all; sP consumed
        if (tid == 0) st_release(myflag, fbase + (unsigned)t + 2u);

        // ---- [E] per-warp: x-part for t+1 (fills exchange window) ----
        if (t + 1 < TT) {
#pragma unroll
            for (int i = 0; i < 8; ++i) { aA[i] = 0; aB[i] = 0; }
            if (LAYER == 1) wait2(srcflags, 2 * w, fbase + (unsigned)t + 3u, lane);
            if (LAYER == 0) {
                float4 v = *reinterpret_cast<const float4*>(xsrc0 + (size_t)(t + 1) * DD);
                xdst0[0] = v.x; xdst0[16] = v.y; xdst0[32] = v.z; xdst0[48] = v.w;
            } else {
                const float4* src = reinterpret_cast<const float4*>(in0) +
                                    ((size_t)((t + 1) * NGRP + grp) * KIN + w * XQ) * 4;
                float4* dst = reinterpret_cast<float4*>(sV) + (w * XQ) * 4;
#pragma unroll
                for (int i = 0; i < XQ / 8; ++i) dst[lane + 32 * i] = __ldcv(src + lane + 32 * i);
            }
            __syncwarp(0xFFFFFFFFu);
            gemm_part<XQ / 4>(wAx, wBx, vx, aA, aB);
        }
    }
}

__global__ void __launch_bounds__(NT, 1) rnn_fused(
    const float* __restrict__ x,
    const float* __restrict__ Wih0, const float* __restrict__ Whh0,
    const float* __restrict__ bih0, const float* __restrict__ bhh0,
    const float* __restrict__ Wih1, const float* __restrict__ Whh1,
    const float* __restrict__ bih1, const float* __restrict__ bhh1)
{
    int bid   = blockIdx.x;
    int layer = bid >> 6;
    int sub   = bid & 63;
    int grp   = sub >> 4;
    int slice = sub & 15;

    if (layer == 0) {
        layer_body<DD, 0>(x, Wih0, Whh0, bih0, bhh0, d_hbA, d_h1s, grp, slice);
    } else {
        layer_body<HH, 1>(d_h1s, Wih1, Whh1, bih1, bhh1, d_hbB, nullptr, grp, slice);
    }
}

// out[b] = dot(h2_last[b][:], fc_w) + fc_b
__global__ void fc_kernel(const float* __restrict__ fcw,
                          const float* __restrict__ fcb,
                          float* __restrict__ out)
{
    int b = blockIdx.x, tid = threadIdx.x;
    const float* h = d_h2s + (size_t)b * HH;
    float s = 0.f;
    for (int k = tid; k < HH; k += 128) s += h[k] * fcw[k];
    for (int o = 16; o > 0; o >>= 1) s += __shfl_xor_sync(0xFFFFFFFFu, s, o);
    __shared__ float ws[4];
    if ((tid & 31) == 0) ws[tid >> 5] = s;
    __syncthreads();
    if (tid == 0) out[b] = ws[0] + ws[1] + ws[2] + ws[3] + fcb[0];
}

extern "C" void kernel_launch(void* const* d_in, const int* in_sizes, int n_in,
                              void* d_out, int out_size)
{
    const float* x     = (const float*)d_in[0];
    const float* W_ih0 = (const float*)d_in[1];
    const float* W_hh0 = (const float*)d_in[2];
    const float* b_ih0 = (const float*)d_in[3];
    const float* b_hh0 = (const float*)d_in[4];
    const float* W_ih1 = (const float*)d_in[5];
    const float* W_hh1 = (const float*)d_in[6];
    const float* b_ih1 = (const float*)d_in[7];
    const float* b_hh1 = (const float*)d_in[8];
    const float* fc_w  = (const float*)d_in[9];
    const float* fc_b  = (const float*)d_in[10];
    float* out = (float*)d_out;

    // smem sized for layer-1 layout: sW + sV + sP + sB + sC
    const int SMB = (64 * (HH + HH + 4) + (HH + HH) * 16 + 8 * 64 * 18 + 64 + 256) * 4; // 203,008

    cudaFuncSetAttribute(rnn_fused, cudaFuncAttributeMaxDynamicSharedMemorySize, SMB);

    rnn_fused<<<128, NT, SMB>>>(x, W_ih0, W_hh0, b_ih0, b_hh0,
                                W_ih1, W_hh1, b_ih1, b_hh1);
    fc_kernel<<<BB, 128>>>(fc_w, fc_b, out);
}